// round 12
// baseline (speedup 1.0000x reference)
#include <cuda_runtime.h>
#include <math_constants.h>

#define NB 64
#define NC 1000
#define HW 196
#define NF4 49
#define GY 8                              // blocks per batch
#define RPB 125                           // rows (classes) per block
#define RPAD 198                          // padded row stride in smem floats
#define HALF 98                           // elements per half-row
#define NKW GY                            // kp partials per batch
#define C4L2E 5.770780163555852f          // 4 * log2(e)
#define RC4L2E 0.17328679513998632f       // 1 / C4L2E
#define LN2   0.6931471805599453f
#define L2E   1.4426950408889634f
#define CLIP2 (-19.931568569324174f)      // log2(1e-6)

// dynamic smem layout (floats)
#define SU_FLOATS 24752                   // RPB*RPAD = 24750, padded to 16B mult
#define TNU_OFF   SU_FLOATS               // 196 floats (49 float4)
#define FG_OFF    (SU_FLOATS + 196)       // 196 ints
#define MISC_OFF  (SU_FLOATS + 392)       // [0]=n1, [1]=n1lo, [2..9] warp red
#define SMEM_FLOATS (MISC_OFF + 16)
#define SMEM_BYTES  (SMEM_FLOATS * 4)

__device__ float g_abl[NB * NC];
__device__ float g_kpw[NB * NKW];
__device__ float g_ace[NB];
__device__ float g_kld[NB];
__device__ int   g_bcnt[NB];              // zero-init; reset by final block
__device__ int   g_done = 0;

__device__ __forceinline__ float ex2f(float x) {
    float r; asm("ex2.approx.f32 %0, %1;" : "=f"(r) : "f"(x)); return r;
}
__device__ __forceinline__ float warpSum(float v) {
#pragma unroll
    for (int o = 16; o; o >>= 1) v += __shfl_xor_sync(0xffffffffu, v, o);
    return v;
}
__device__ __forceinline__ float warpMax(float v) {
#pragma unroll
    for (int o = 16; o; o >>= 1) v = fmaxf(v, __shfl_xor_sync(0xffffffffu, v, o));
    return v;
}

// ---------------------------------------------------------------------------
// Fused kernel. grid=(NB, GY), block=256. Thread-PAIR per row.
// Stage: 125 rows coalesced gmem -> smem, converting a -> u = C4L2E*a + tnu.
// Compute: thread pair (2r, 2r+1) owns row r; each thread scans 98 elements
// serially from smem (no padding waste, no butterflies). fg-dependent sums
// iterate a ballot-compacted index list (row-invariant positions).
// Phase B: 8th block per batch reduces 1000 abl + 8 kp partials.
// Phase C: 64th batch-finisher -> scalar; resets counters (replay-safe).
// All reduction orders fixed -> deterministic.
// ---------------------------------------------------------------------------
__global__ __launch_bounds__(256) void k1(const float* __restrict__ cams,
                                          const int* __restrict__ y0,
                                          const int* __restrict__ labels,
                                          float* __restrict__ out) {
    extern __shared__ float sm[];
    float*  su     = sm;                       // [RPB][RPAD] u values
    float4* s_tnu4 = (float4*)(sm + TNU_OFF);  // 49 float4
    int*    s_fg   = (int*)(sm + FG_OFF);      // fg position list
    float*  s_misc = sm + MISC_OFF;
    __shared__ float s_red;
    __shared__ int   s_flag;

    const int b   = blockIdx.x;
    const int tid = threadIdx.x;
    const int warp = tid >> 5;
    const int lane = tid & 31;
    const int label = __ldg(labels + b);
    const float* base = cams + (size_t)b * NC * HW;
    const int c0 = blockIdx.y * RPB;

    // ---- tnu (warp 0 range) + fg compaction (warp 1) -----------------------
    if (tid < NF4) {
        const float4 t4 = __ldg((const float4*)(base + (size_t)label * HW) + tid);
        s_tnu4[tid] = make_float4(-C4L2E * t4.x, -C4L2E * t4.y,
                                  -C4L2E * t4.z, -C4L2E * t4.w);
    }
    if (warp == 1) {
        int run = 0, runlo = 0;
        for (int bi = 0; bi < HW; bi += 32) {
            const int i = bi + lane;
            const int f = (i < HW) ? __ldg(y0 + b * HW + i) : 0;
            const unsigned m  = __ballot_sync(0xffffffffu, f != 0);
            const unsigned ml = __ballot_sync(0xffffffffu, f != 0 && i < HALF);
            if (f) s_fg[run + __popc(m & ((1u << lane) - 1u))] = i;
            run   += __popc(m);
            runlo += __popc(ml);
        }
        if (lane == 0) { s_misc[0] = (float)run; s_misc[1] = (float)runlo; }
    }
    __syncthreads();

    // ---- staging: gmem (coalesced float4) -> smem u ------------------------
    {
        const float4* g4 = (const float4*)(base + (size_t)c0 * HW);
        for (int e = tid; e < RPB * NF4; e += 256) {
            const int r = e / NF4;
            const int s = e - r * NF4;
            const float4 a4 = __ldg(g4 + (size_t)r * NF4 + s);
            const float4 t4 = s_tnu4[s];
            float2* dst = (float2*)(su + r * RPAD + 4 * s);
            dst[0] = make_float2(fmaf(C4L2E, a4.x, t4.x), fmaf(C4L2E, a4.y, t4.y));
            dst[1] = make_float2(fmaf(C4L2E, a4.z, t4.z), fmaf(C4L2E, a4.w, t4.w));
        }
    }
    __syncthreads();

    const float n1  = s_misc[0];
    const int  n1i  = (int)s_misc[0];
    const int  nlo  = (int)s_misc[1];

    // ---- compute: thread pair per row --------------------------------------
    float kpacc = 0.f;
    {
        const int r0 = tid >> 1;                // nominal row
        const int r  = (r0 < RPB) ? r0 : (RPB - 1);   // clamp (keeps shfl converged)
        const int h  = tid & 1;
        const float* up = su + r * RPAD + h * HALF;

        float d0 = 0.f, d1 = 0.f, d2 = 0.f, d3 = 0.f;
        float sa0 = 0.f, sa1 = 0.f;
        for (int j = 0; j < 96; j += 4) {
            const float u0 = up[j], u1 = up[j + 1], u2 = up[j + 2], u3 = up[j + 3];
            d0 += ex2f(u0); d1 += ex2f(u1); d2 += ex2f(u2); d3 += ex2f(u3);
            sa0 += fabsf(u0); sa1 += fabsf(u1); sa0 += fabsf(u2); sa1 += fabsf(u3);
        }
        {
            const float u0 = up[96], u1 = up[97];
            d0 += ex2f(u0); d1 += ex2f(u1);
            sa0 += fabsf(u0); sa1 += fabsf(u1);
        }
        float den  = (d0 + d1) + (d2 + d3);
        float sabs = sa0 + sa1;
        den += __shfl_xor_sync(0xffffffffu, den, 1);      // pair combine
        const float L2 = __log2f(den);
        const float Lc = L2 + CLIP2;

        // fg pass over this half's indices
        const int j0 = h ? nlo : 0;
        const int j1 = h ? n1i : nlo;
        float corr = 0.f, ka = 0.f;
        const float* rowp = su + r * RPAD;
        for (int j = j0; j < j1; j++) {
            const float u = rowp[s_fg[j]];
            corr += fmaxf(u, 0.f);
            ka   += fmaxf(u, Lc);
        }
        float s1 = sabs - 2.f * corr;
        s1 += __shfl_xor_sync(0xffffffffu, s1, 1);
        ka += __shfl_xor_sync(0xffffffffu, ka, 1);

        if (h == 0 && r0 < RPB) {
            g_abl[b * NC + c0 + r0] = s1 * RC4L2E;
            kpacc = ka - n1 * L2;
        }
    }

    // ---- block kp reduction -> one partial per block -----------------------
    float kp = warpSum(kpacc);
    if (lane == 0) s_misc[2 + warp] = kp;
    __syncthreads();
    if (tid == 0) {
        float t = 0.f;
        for (int i = 0; i < 8; i++) t += s_misc[2 + i];
        g_kpw[b * NKW + blockIdx.y] = -LN2 * t;
    }

    // ---------------- Phase B election: last block of this batch ------------
    __syncthreads();
    if (tid == 0) {
        __threadfence();                        // release g_abl/g_kpw stores
        s_flag = (atomicAdd(&g_bcnt[b], 1) == GY - 1);
    }
    __syncthreads();
    if (!s_flag) return;

    // ---------------- Phase B: per-batch reduction (L2-hot) -----------------
    __threadfence();                            // acquire peers' stores
    const float* abl = g_abl + b * NC;
    const float* kwp = g_kpw + b * NKW;

    float mx = -CUDART_INF_F;
    for (int c = tid; c < NC; c += 256) mx = fmaxf(mx, abl[c]);
    mx = warpMax(mx);
    if (lane == 0) s_misc[2 + warp] = mx;
    __syncthreads();
    if (warp == 0) {
        float m2 = (lane < 8) ? s_misc[2 + lane] : -CUDART_INF_F;
        m2 = warpMax(m2);
        if (lane == 0) s_red = m2;
    }
    __syncthreads();
    const float bmax = s_red;

    float se = 0.f, sa = 0.f;
    for (int c = tid; c < NC; c += 256) {
        const float a = abl[c];
        se += ex2f((a - bmax) * L2E);
        sa += a;
    }
    float sk = (tid < NKW) ? kwp[tid] : 0.f;
    se = warpSum(se); sa = warpSum(sa); sk = warpSum(sk);
    __syncthreads();
    if (lane == 0) {
        s_misc[2 + warp]  = se;
        s_misc[10 + warp] = sa;
    }
    if (tid == 0) s_misc[1] = sk;               // warp 0 holds full sk
    __syncthreads();

    if (tid == 0) {
        float se_t = 0.f, sa_t = 0.f;
        for (int i = 0; i < 8; i++) { se_t += s_misc[2 + i]; sa_t += s_misc[10 + i]; }
        const float sk_t = s_misc[1];
        const float L = __logf(se_t);
        const float al = abl[label];
        const float ace = -(0.9f * (al - bmax - L) +
                            1e-4f * (sa_t - (float)NC * (bmax + L)));
        float p1 = 0.f;
        if (n1 > 0.f) p1 = 1.f / (n1 + ((float)HW - n1) * __expf(-10.f));
        g_ace[b] = ace;
        g_kld[b] = p1 * sk_t;
        __threadfence();
        s_flag = (atomicAdd(&g_done, 1) == NB - 1);
    }
    __syncthreads();
    if (!s_flag) return;

    // ---------------- Phase C: final 64 -> 1 + counter reset ----------------
    if (warp == 0) {
        __threadfence();                        // acquire all g_ace/g_kld
        float a = g_ace[lane] + g_ace[lane + 32];
        float k = g_kld[lane] + g_kld[lane + 32];
        a = warpSum(a);
        k = warpSum(k);
        g_bcnt[lane] = 0;
        g_bcnt[lane + 32] = 0;
        if (lane == 0) {
            out[0] = (a + 0.5f * k) * (1.0f / NB);
            g_done = 0;
        }
    }
}

extern "C" void kernel_launch(void* const* d_in, const int* in_sizes, int n_in,
                              void* d_out, int out_size) {
    const float* cams  = (const float*)d_in[0];
    const int* y0      = (const int*)d_in[1];
    const int* labels  = (const int*)d_in[2];
    float* out = (float*)d_out;

    cudaFuncSetAttribute(k1, cudaFuncAttributeMaxDynamicSharedMemorySize,
                         SMEM_BYTES);
    k1<<<dim3(NB, GY), 256, SMEM_BYTES>>>(cams, y0, labels, out);
}

// round 13
// speedup vs baseline: 1.1579x; 1.1579x over previous
#include <cuda_runtime.h>
#include <math_constants.h>

#define NB 64
#define NC 1000
#define HW 196
#define NF4 49
#define GY 25                             // blocks per batch
#define CPB (NC / GY)                     // 40 classes per block -> 5 rows/warp
#define C4L2E 5.770780163555852f          // 4 * log2(e)
#define RC4L2E 0.17328679513998632f       // 1 / C4L2E
#define LN2   0.6931471805599453f
#define L2E   1.4426950408889634f
#define CLIP2 (-19.931568569324174f)      // log2(1e-6)
#define DEADB (-24000.0f)                 // u bias for dead lane-slots: 2^u == 0

// per-(batch,block) partials: hierarchical reductions, no per-class array
__device__ float g_bmx[NB * GY];
__device__ float g_bse[NB * GY];
__device__ float g_bsa[NB * GY];
__device__ float g_bkp[NB * GY];
__device__ float g_al[NB];                // abl[label] scalar
__device__ float g_ace[NB];
__device__ float g_kld[NB];
__device__ int   g_bcnt[NB];              // zero-init; reset by final block
__device__ int   g_done = 0;

__device__ __forceinline__ float ex2f(float x) {
    float r; asm("ex2.approx.f32 %0, %1;" : "=f"(r) : "f"(x)); return r;
}
__device__ __forceinline__ float warpSum(float v) {
#pragma unroll
    for (int o = 16; o; o >>= 1) v += __shfl_xor_sync(0xffffffffu, v, o);
    return v;
}
__device__ __forceinline__ float warpMax(float v) {
#pragma unroll
    for (int o = 16; o; o >>= 1) v = fmaxf(v, __shfl_xor_sync(0xffffffffu, v, o));
    return v;
}

// ---------------------------------------------------------------------------
// Fused kernel. grid=(NB, GY), block=256 (8 warps, exactly 5 rows/warp).
// Phase A: R7 loop body (u-direct, warp-per-row). Instead of storing per-class
// abl, each warp keeps a streaming logsumexp (mxw, sew) + plain sum saw over
// its 5 abl values (warp-uniform registers). abl[label] caught via one
// predicated store.
// Block epilogue: warp 0 combines 8 warp-partials -> 4 scalars per block.
// Phase B: last-of-batch block combines 25 quadruples (no 1000-elem passes).
// Phase C: last-of-grid warp reduces 64 -> scalar, resets counters.
// All reduction orders fixed -> deterministic.
// ---------------------------------------------------------------------------
__global__ __launch_bounds__(256, 6) void k1(const float* __restrict__ cams,
                                             const int* __restrict__ y0,
                                             const int* __restrict__ labels,
                                             float* __restrict__ out) {
    __shared__ float4 s_tn4[NF4];   // tnu = -C4L2E * target row
    __shared__ float4 s_f4[NF4];    // f2 = 2 * fg mask
    __shared__ float sh_mx[8];
    __shared__ float sh_se[8];
    __shared__ float sh_sa[8];
    __shared__ float sh_kp[8];
    __shared__ int s_flag;

    const int b = blockIdx.x;
    const int tid = threadIdx.x;
    const int label = __ldg(labels + b);
    const float* base = cams + (size_t)b * NC * HW;

    if (tid < HW) {
        ((float*)s_tn4)[tid] = -C4L2E * __ldg(base + (size_t)label * HW + tid);
        ((float*)s_f4)[tid]  = 2.0f * (float)__ldg(y0 + b * HW + tid);
    }
    __syncthreads();

    const int warp = tid >> 5;
    const int lane = tid & 31;
    const bool live = lane < (NF4 - 32);
    const int idx2 = 32 + (live ? lane : 16);     // clamped (slot 48 valid)
    const float m1 = live ? 1.0f : 0.0f;

    const float4 tnu0 = s_tn4[lane];
    const float4 f0   = s_f4[lane];               // f2 values
    float4 tnu1, f1;
    if (live) { tnu1 = s_tn4[idx2]; f1 = s_f4[idx2]; }
    else {
        tnu1 = make_float4(DEADB, DEADB, DEADB, DEADB);
        f1   = make_float4(0.f, 0.f, 0.f, 0.f);
    }

    // row-invariant fg count: n1 = 0.5 * sum(f2)
    float n1 = 0.5f * ((f0.x + f0.y) + (f0.z + f0.w) +
                       (f1.x + f1.y) + (f1.z + f1.w));
    n1 = warpSum(n1);

    const int c0 = blockIdx.y * CPB;
    const float4* row4 = (const float4*)(base + (size_t)(c0 + warp) * HW);
    const size_t rstep = (size_t)8 * NF4;

    float kacc = 0.f;     // per-lane, across rows
    float L2sum = 0.f;    // per-row L2 accumulated (lane-uniform)
    float mxw = -CUDART_INF_F, sew = 0.f, saw = 0.f;   // streaming lse (uniform)

#pragma unroll 1
    for (int cl = warp; cl < CPB; cl += 8, row4 += rstep) {
        const float4 a0 = __ldg(row4 + lane);
        const float4 a1 = __ldg(row4 + idx2);

        float u[8];
        float den = 0.f, sabs = 0.f, sfp = 0.f;

        u[0] = fmaf(C4L2E, a0.x, tnu0.x); den += ex2f(u[0]);
        sabs += fabsf(u[0]); sfp = fmaf(f0.x, fmaxf(u[0], 0.f), sfp);
        u[1] = fmaf(C4L2E, a0.y, tnu0.y); den += ex2f(u[1]);
        sabs += fabsf(u[1]); sfp = fmaf(f0.y, fmaxf(u[1], 0.f), sfp);
        u[2] = fmaf(C4L2E, a0.z, tnu0.z); den += ex2f(u[2]);
        sabs += fabsf(u[2]); sfp = fmaf(f0.z, fmaxf(u[2], 0.f), sfp);
        u[3] = fmaf(C4L2E, a0.w, tnu0.w); den += ex2f(u[3]);
        sabs += fabsf(u[3]); sfp = fmaf(f0.w, fmaxf(u[3], 0.f), sfp);

        u[4] = fmaf(C4L2E, a1.x, tnu1.x); den += ex2f(u[4]);
        sabs = fmaf(m1, fabsf(u[4]), sabs); sfp = fmaf(f1.x, fmaxf(u[4], 0.f), sfp);
        u[5] = fmaf(C4L2E, a1.y, tnu1.y); den += ex2f(u[5]);
        sabs = fmaf(m1, fabsf(u[5]), sabs); sfp = fmaf(f1.y, fmaxf(u[5], 0.f), sfp);
        u[6] = fmaf(C4L2E, a1.z, tnu1.z); den += ex2f(u[6]);
        sabs = fmaf(m1, fabsf(u[6]), sabs); sfp = fmaf(f1.z, fmaxf(u[6], 0.f), sfp);
        u[7] = fmaf(C4L2E, a1.w, tnu1.w); den += ex2f(u[7]);
        sabs = fmaf(m1, fabsf(u[7]), sabs); sfp = fmaf(f1.w, fmaxf(u[7], 0.f), sfp);

        den = warpSum(den);
        const float L2 = __log2f(den);
        const float Lc = L2 + CLIP2;
        L2sum += L2;

        kacc = fmaf(f0.x, fmaxf(u[0], Lc), kacc);
        kacc = fmaf(f0.y, fmaxf(u[1], Lc), kacc);
        kacc = fmaf(f0.z, fmaxf(u[2], Lc), kacc);
        kacc = fmaf(f0.w, fmaxf(u[3], Lc), kacc);
        kacc = fmaf(f1.x, fmaxf(u[4], Lc), kacc);
        kacc = fmaf(f1.y, fmaxf(u[5], Lc), kacc);
        kacc = fmaf(f1.z, fmaxf(u[6], Lc), kacc);
        kacc = fmaf(f1.w, fmaxf(u[7], Lc), kacc);

        const float s1 = warpSum(sabs - sfp);
        const float a = s1 * RC4L2E;              // this row's abl (uniform)

        // streaming logsumexp + sum (warp-uniform, no stores)
        saw += a;
        const float nm = fmaxf(mxw, a);
        sew = fmaf(sew, ex2f((mxw - nm) * L2E), ex2f((a - nm) * L2E));
        mxw = nm;

        // catch abl[label] (exactly one row in the whole grid)
        if (lane == 0 && (c0 + cl) == label) g_al[b] = a;
    }

    // per-warp partials -> smem
    kacc = warpSum(kacc);
    if (lane == 0) {
        sh_mx[warp] = mxw;
        sh_se[warp] = sew;
        sh_sa[warp] = saw;
        sh_kp[warp] = -LN2 * (0.5f * kacc - n1 * L2sum);
    }
    __syncthreads();

    // warp 0: combine 8 warp-partials -> 4 scalars for this block
    if (warp == 0) {
        const bool v = lane < 8;
        float m  = v ? sh_mx[lane] : -CUDART_INF_F;
        float se = v ? sh_se[lane] : 0.f;
        float sa = v ? sh_sa[lane] : 0.f;
        float kp = v ? sh_kp[lane] : 0.f;
        const float M = warpMax(m);
        se = se * ex2f((m - M) * L2E);            // -inf lanes -> 0
        se = warpSum(se); sa = warpSum(sa); kp = warpSum(kp);
        if (lane == 0) {
            const int gi = b * GY + blockIdx.y;
            g_bmx[gi] = M; g_bse[gi] = se; g_bsa[gi] = sa; g_bkp[gi] = kp;
        }
    }
    __syncthreads();

    // ---------------- Phase B election: last block of this batch ------------
    if (tid == 0) {
        __threadfence();                        // release this block's partials
        s_flag = (atomicAdd(&g_bcnt[b], 1) == GY - 1);
    }
    __syncthreads();
    if (!s_flag || warp != 0) return;

    // ---------------- Phase B: combine 25 block-partials (warp 0 only) ------
    __threadfence();                            // acquire peers' partials
    {
        const bool v = lane < GY;
        const int gi = b * GY + (v ? lane : 0);
        float m  = v ? g_bmx[gi] : -CUDART_INF_F;
        float se = v ? g_bse[gi] : 0.f;
        float sa = v ? g_bsa[gi] : 0.f;
        float kp = v ? g_bkp[gi] : 0.f;
        const float bmax = warpMax(m);
        se = se * ex2f((m - bmax) * L2E);
        se = warpSum(se); sa = warpSum(sa); kp = warpSum(kp);

        int lastg = 0;
        if (lane == 0) {
            const float L = __logf(se);
            const float al = g_al[b];
            const float ace = -(0.9f * (al - bmax - L) +
                                1e-4f * (sa - (float)NC * (bmax + L)));
            float p1 = 0.f;
            if (n1 > 0.f) p1 = 1.f / (n1 + ((float)HW - n1) * __expf(-10.f));
            g_ace[b] = ace;
            g_kld[b] = p1 * kp;
            __threadfence();
            lastg = (atomicAdd(&g_done, 1) == NB - 1);
        }
        lastg = __shfl_sync(0xffffffffu, lastg, 0);
        if (!lastg) return;
    }

    // ---------------- Phase C: final 64 -> 1 + counter reset ----------------
    __threadfence();                            // acquire all g_ace/g_kld
    {
        float a = g_ace[lane] + g_ace[lane + 32];
        float k = g_kld[lane] + g_kld[lane + 32];
        a = warpSum(a);
        k = warpSum(k);
        g_bcnt[lane] = 0;
        g_bcnt[lane + 32] = 0;
        if (lane == 0) {
            out[0] = (a + 0.5f * k) * (1.0f / NB);
            g_done = 0;
        }
    }
}

extern "C" void kernel_launch(void* const* d_in, const int* in_sizes, int n_in,
                              void* d_out, int out_size) {
    const float* cams  = (const float*)d_in[0];
    const int* y0      = (const int*)d_in[1];
    const int* labels  = (const int*)d_in[2];
    float* out = (float*)d_out;

    k1<<<dim3(NB, GY), 256>>>(cams, y0, labels, out);
}

// round 14
// speedup vs baseline: 1.2794x; 1.1050x over previous
#include <cuda_runtime.h>
#include <math_constants.h>

#define NB 64
#define NC 1000
#define HW 196
#define NF4 49
#define GY 25                             // blocks per batch
#define CPB (NC / GY)                     // 40 classes per block -> 5 rows/warp
#define NROW 5                            // rows per warp (compile-time)
#define C4L2E 5.770780163555852f          // 4 * log2(e)
#define RC4L2E 0.17328679513998632f       // 1 / C4L2E
#define LN2   0.6931471805599453f
#define L2E   1.4426950408889634f
#define CLIP2 (-19.931568569324174f)      // log2(1e-6)
#define DEADB (-24000.0f)                 // u bias for dead lane-slots: 2^u == 0

// hierarchical partials (no per-class arrays)
__device__ float g_bmx[NB * GY];
__device__ float g_bse[NB * GY];
__device__ float g_bsa[NB * GY];
__device__ float g_bkp[NB * GY];
__device__ float g_al[NB];                // abl[label] scalar
__device__ float g_ace[NB];
__device__ float g_kld[NB];
__device__ int   g_bcnt[NB];              // zero-init; reset by final block
__device__ int   g_done = 0;

__device__ __forceinline__ float ex2f(float x) {
    float r; asm("ex2.approx.f32 %0, %1;" : "=f"(r) : "f"(x)); return r;
}
__device__ __forceinline__ float warpSum(float v) {
#pragma unroll
    for (int o = 16; o; o >>= 1) v += __shfl_xor_sync(0xffffffffu, v, o);
    return v;
}
__device__ __forceinline__ float warpMax(float v) {
#pragma unroll
    for (int o = 16; o; o >>= 1) v = fmaxf(v, __shfl_xor_sync(0xffffffffu, v, o));
    return v;
}

// ---------------------------------------------------------------------------
// Fused kernel. grid=(NB, GY), block=256 (8 warps; warp w owns rows w+8i,
// i=0..4). FULLY UNROLLED row loop, indexed addressing, NO register cap, NO
// cross-row serial chains: ptxas is free to hoist/batch the 10 LDG.128s
// (this is what made R2 hit 2430 GB/s).
// Per-row: u = C4L2E*a + tnu; den->L2 (one butterfly); abl (one butterfly)
// into a register array; kacc accumulates across rows (post-L2 FADD tail).
// After the loop: lse over the 5 abl registers, kp butterfly, block combine
// -> 4 scalars; last block of batch combines 25; last of grid -> out.
// All reduction orders fixed -> deterministic.
// ---------------------------------------------------------------------------
__global__ __launch_bounds__(256) void k1(const float* __restrict__ cams,
                                          const int* __restrict__ y0,
                                          const int* __restrict__ labels,
                                          float* __restrict__ out) {
    __shared__ float4 s_tn4[NF4];   // tnu = -C4L2E * target row
    __shared__ float4 s_f4[NF4];    // f2 = 2 * fg mask
    __shared__ float sh_mx[8];
    __shared__ float sh_se[8];
    __shared__ float sh_sa[8];
    __shared__ float sh_kp[8];
    __shared__ int s_flag;

    const int b = blockIdx.x;
    const int tid = threadIdx.x;
    const int label = __ldg(labels + b);
    const float* base = cams + (size_t)b * NC * HW;

    if (tid < HW) {
        ((float*)s_tn4)[tid] = -C4L2E * __ldg(base + (size_t)label * HW + tid);
        ((float*)s_f4)[tid]  = 2.0f * (float)__ldg(y0 + b * HW + tid);
    }
    __syncthreads();

    const int warp = tid >> 5;
    const int lane = tid & 31;
    const bool live = lane < (NF4 - 32);
    const int idx2 = 32 + (live ? lane : 16);     // clamped (slot 48 valid)
    const float m1 = live ? 1.0f : 0.0f;

    const float4 tnu0 = s_tn4[lane];
    const float4 f0   = s_f4[lane];               // f2 values
    float4 tnu1, f1;
    if (live) { tnu1 = s_tn4[idx2]; f1 = s_f4[idx2]; }
    else {
        tnu1 = make_float4(DEADB, DEADB, DEADB, DEADB);
        f1   = make_float4(0.f, 0.f, 0.f, 0.f);
    }

    // row-invariant fg count: n1 = 0.5 * sum(f2)
    float n1 = 0.5f * ((f0.x + f0.y) + (f0.z + f0.w) +
                       (f1.x + f1.y) + (f1.z + f1.w));
    n1 = warpSum(n1);

    const int c0 = blockIdx.y * CPB;
    float kacc = 0.f;      // per-lane, across rows
    float L2sum = 0.f;     // lane-uniform
    float abl[NROW];       // per-row abl values (register array, full unroll)

#pragma unroll
    for (int i = 0; i < NROW; i++) {
        const int cl = warp + 8 * i;              // < CPB always
        const float4* row4 = (const float4*)(base + (size_t)(c0 + cl) * HW);
        const float4 a0 = __ldg(row4 + lane);
        const float4 a1 = __ldg(row4 + idx2);

        float u[8];
        float den = 0.f, sabs = 0.f, sfp = 0.f;

        u[0] = fmaf(C4L2E, a0.x, tnu0.x); den += ex2f(u[0]);
        sabs += fabsf(u[0]); sfp = fmaf(f0.x, fmaxf(u[0], 0.f), sfp);
        u[1] = fmaf(C4L2E, a0.y, tnu0.y); den += ex2f(u[1]);
        sabs += fabsf(u[1]); sfp = fmaf(f0.y, fmaxf(u[1], 0.f), sfp);
        u[2] = fmaf(C4L2E, a0.z, tnu0.z); den += ex2f(u[2]);
        sabs += fabsf(u[2]); sfp = fmaf(f0.z, fmaxf(u[2], 0.f), sfp);
        u[3] = fmaf(C4L2E, a0.w, tnu0.w); den += ex2f(u[3]);
        sabs += fabsf(u[3]); sfp = fmaf(f0.w, fmaxf(u[3], 0.f), sfp);

        u[4] = fmaf(C4L2E, a1.x, tnu1.x); den += ex2f(u[4]);
        sabs = fmaf(m1, fabsf(u[4]), sabs); sfp = fmaf(f1.x, fmaxf(u[4], 0.f), sfp);
        u[5] = fmaf(C4L2E, a1.y, tnu1.y); den += ex2f(u[5]);
        sabs = fmaf(m1, fabsf(u[5]), sabs); sfp = fmaf(f1.y, fmaxf(u[5], 0.f), sfp);
        u[6] = fmaf(C4L2E, a1.z, tnu1.z); den += ex2f(u[6]);
        sabs = fmaf(m1, fabsf(u[6]), sabs); sfp = fmaf(f1.z, fmaxf(u[6], 0.f), sfp);
        u[7] = fmaf(C4L2E, a1.w, tnu1.w); den += ex2f(u[7]);
        sabs = fmaf(m1, fabsf(u[7]), sabs); sfp = fmaf(f1.w, fmaxf(u[7], 0.f), sfp);

        den = warpSum(den);
        const float L2 = __log2f(den);
        const float Lc = L2 + CLIP2;
        L2sum += L2;

        kacc = fmaf(f0.x, fmaxf(u[0], Lc), kacc);
        kacc = fmaf(f0.y, fmaxf(u[1], Lc), kacc);
        kacc = fmaf(f0.z, fmaxf(u[2], Lc), kacc);
        kacc = fmaf(f0.w, fmaxf(u[3], Lc), kacc);
        kacc = fmaf(f1.x, fmaxf(u[4], Lc), kacc);
        kacc = fmaf(f1.y, fmaxf(u[5], Lc), kacc);
        kacc = fmaf(f1.z, fmaxf(u[6], Lc), kacc);
        kacc = fmaf(f1.w, fmaxf(u[7], Lc), kacc);

        const float s1 = warpSum(sabs - sfp);
        abl[i] = s1 * RC4L2E;

        if (lane == 0 && (c0 + cl) == label) g_al[b] = abl[i];
    }

    // lse + sum over the 5 per-row abl values (once, after the loop)
    float mxw = abl[0];
#pragma unroll
    for (int i = 1; i < NROW; i++) mxw = fmaxf(mxw, abl[i]);
    float sew = 0.f, saw = 0.f;
#pragma unroll
    for (int i = 0; i < NROW; i++) {
        sew += ex2f((abl[i] - mxw) * L2E);
        saw += abl[i];
    }

    kacc = warpSum(kacc);
    if (lane == 0) {
        sh_mx[warp] = mxw;
        sh_se[warp] = sew;
        sh_sa[warp] = saw;
        sh_kp[warp] = -LN2 * (0.5f * kacc - n1 * L2sum);
    }
    __syncthreads();

    // warp 0: combine 8 warp-partials -> 4 scalars for this block
    if (warp == 0) {
        const bool v = lane < 8;
        float m  = v ? sh_mx[lane] : -CUDART_INF_F;
        float se = v ? sh_se[lane] : 0.f;
        float sa = v ? sh_sa[lane] : 0.f;
        float kp = v ? sh_kp[lane] : 0.f;
        const float M = warpMax(m);
        se = se * ex2f((m - M) * L2E);            // -inf lanes -> 0
        se = warpSum(se); sa = warpSum(sa); kp = warpSum(kp);
        if (lane == 0) {
            const int gi = b * GY + blockIdx.y;
            g_bmx[gi] = M; g_bse[gi] = se; g_bsa[gi] = sa; g_bkp[gi] = kp;
        }
    }
    __syncthreads();

    // ---------------- Phase B election: last block of this batch ------------
    if (tid == 0) {
        __threadfence();                        // release this block's partials
        s_flag = (atomicAdd(&g_bcnt[b], 1) == GY - 1);
    }
    __syncthreads();
    if (!s_flag || warp != 0) return;

    // ---------------- Phase B: combine 25 block-partials (warp 0 only) ------
    __threadfence();                            // acquire peers' partials
    {
        const bool v = lane < GY;
        const int gi = b * GY + (v ? lane : 0);
        float m  = v ? g_bmx[gi] : -CUDART_INF_F;
        float se = v ? g_bse[gi] : 0.f;
        float sa = v ? g_bsa[gi] : 0.f;
        float kp = v ? g_bkp[gi] : 0.f;
        const float bmax = warpMax(m);
        se = se * ex2f((m - bmax) * L2E);
        se = warpSum(se); sa = warpSum(sa); kp = warpSum(kp);

        int lastg = 0;
        if (lane == 0) {
            const float L = __logf(se);
            const float al = g_al[b];
            const float ace = -(0.9f * (al - bmax - L) +
                                1e-4f * (sa - (float)NC * (bmax + L)));
            float p1 = 0.f;
            if (n1 > 0.f) p1 = 1.f / (n1 + ((float)HW - n1) * __expf(-10.f));
            g_ace[b] = ace;
            g_kld[b] = p1 * kp;
            __threadfence();
            lastg = (atomicAdd(&g_done, 1) == NB - 1);
        }
        lastg = __shfl_sync(0xffffffffu, lastg, 0);
        if (!lastg) return;
    }

    // ---------------- Phase C: final 64 -> 1 + counter reset ----------------
    __threadfence();                            // acquire all g_ace/g_kld
    {
        float a = g_ace[lane] + g_ace[lane + 32];
        float k = g_kld[lane] + g_kld[lane + 32];
        a = warpSum(a);
        k = warpSum(k);
        g_bcnt[lane] = 0;
        g_bcnt[lane + 32] = 0;
        if (lane == 0) {
            out[0] = (a + 0.5f * k) * (1.0f / NB);
            g_done = 0;
        }
    }
}

extern "C" void kernel_launch(void* const* d_in, const int* in_sizes, int n_in,
                              void* d_out, int out_size) {
    const float* cams  = (const float*)d_in[0];
    const int* y0      = (const int*)d_in[1];
    const int* labels  = (const int*)d_in[2];
    float* out = (float*)d_out;

    k1<<<dim3(NB, GY), 256>>>(cams, y0, labels, out);
}

// round 15
// speedup vs baseline: 1.3323x; 1.0414x over previous
#include <cuda_runtime.h>
#include <math_constants.h>

#define NB 64
#define NC 1000
#define HW 196
#define NF4 49
#define GY 25                             // blocks per batch
#define CPB (NC / GY)                     // 40 classes per block -> 5 rows/warp
#define NROW 5                            // rows per warp (compile-time)
#define C4L2E 5.770780163555852f          // 4 * log2(e)
#define RC4L2E 0.17328679513998632f       // 1 / C4L2E
#define LN2   0.6931471805599453f
#define L2E   1.4426950408889634f
#define CLIP2 (-19.931568569324174f)      // log2(1e-6)
#define DEADB (-24000.0f)                 // u bias for dead lane-slots: 2^u == 0

// hierarchical partials (no per-class arrays)
__device__ float g_bmx[NB * GY];
__device__ float g_bse[NB * GY];
__device__ float g_bsa[NB * GY];
__device__ float g_bkp[NB * GY];
__device__ float g_al[NB];                // abl[label] scalar
__device__ float g_ace[NB];
__device__ float g_kld[NB];
__device__ int   g_bcnt[NB];              // zero-init; reset by final block
__device__ int   g_done = 0;

__device__ __forceinline__ float ex2f(float x) {
    float r; asm("ex2.approx.f32 %0, %1;" : "=f"(r) : "f"(x)); return r;
}
__device__ __forceinline__ float warpSum(float v) {
#pragma unroll
    for (int o = 16; o; o >>= 1) v += __shfl_xor_sync(0xffffffffu, v, o);
    return v;
}
__device__ __forceinline__ float warpMax(float v) {
#pragma unroll
    for (int o = 16; o; o >>= 1) v = fmaxf(v, __shfl_xor_sync(0xffffffffu, v, o));
    return v;
}

// ---------------------------------------------------------------------------
// Fused kernel. grid=(NB, GY), block=256 (8 warps; warp w owns rows w+8i,
// i=0..4). Fully unrolled row loop, indexed addressing, NO cross-row serial
// chains. Single change vs R14 winner: __launch_bounds__(256, 5) caps regs
// at 48 -> 5 blocks/SM (40 warps, 62.5% theoretical occupancy) while ptxas
// still batches ~2 rows of loads.
// ---------------------------------------------------------------------------
__global__ __launch_bounds__(256, 5) void k1(const float* __restrict__ cams,
                                             const int* __restrict__ y0,
                                             const int* __restrict__ labels,
                                             float* __restrict__ out) {
    __shared__ float4 s_tn4[NF4];   // tnu = -C4L2E * target row
    __shared__ float4 s_f4[NF4];    // f2 = 2 * fg mask
    __shared__ float sh_mx[8];
    __shared__ float sh_se[8];
    __shared__ float sh_sa[8];
    __shared__ float sh_kp[8];
    __shared__ int s_flag;

    const int b = blockIdx.x;
    const int tid = threadIdx.x;
    const int label = __ldg(labels + b);
    const float* base = cams + (size_t)b * NC * HW;

    if (tid < HW) {
        ((float*)s_tn4)[tid] = -C4L2E * __ldg(base + (size_t)label * HW + tid);
        ((float*)s_f4)[tid]  = 2.0f * (float)__ldg(y0 + b * HW + tid);
    }
    __syncthreads();

    const int warp = tid >> 5;
    const int lane = tid & 31;
    const bool live = lane < (NF4 - 32);
    const int idx2 = 32 + (live ? lane : 16);     // clamped (slot 48 valid)
    const float m1 = live ? 1.0f : 0.0f;

    const float4 tnu0 = s_tn4[lane];
    const float4 f0   = s_f4[lane];               // f2 values
    float4 tnu1, f1;
    if (live) { tnu1 = s_tn4[idx2]; f1 = s_f4[idx2]; }
    else {
        tnu1 = make_float4(DEADB, DEADB, DEADB, DEADB);
        f1   = make_float4(0.f, 0.f, 0.f, 0.f);
    }

    // row-invariant fg count: n1 = 0.5 * sum(f2)
    float n1 = 0.5f * ((f0.x + f0.y) + (f0.z + f0.w) +
                       (f1.x + f1.y) + (f1.z + f1.w));
    n1 = warpSum(n1);

    const int c0 = blockIdx.y * CPB;
    float kacc = 0.f;      // per-lane, across rows
    float L2sum = 0.f;     // lane-uniform
    float abl[NROW];       // per-row abl values (register array, full unroll)

#pragma unroll
    for (int i = 0; i < NROW; i++) {
        const int cl = warp + 8 * i;              // < CPB always
        const float4* row4 = (const float4*)(base + (size_t)(c0 + cl) * HW);
        const float4 a0 = __ldg(row4 + lane);
        const float4 a1 = __ldg(row4 + idx2);

        float u[8];
        float den = 0.f, sabs = 0.f, sfp = 0.f;

        u[0] = fmaf(C4L2E, a0.x, tnu0.x); den += ex2f(u[0]);
        sabs += fabsf(u[0]); sfp = fmaf(f0.x, fmaxf(u[0], 0.f), sfp);
        u[1] = fmaf(C4L2E, a0.y, tnu0.y); den += ex2f(u[1]);
        sabs += fabsf(u[1]); sfp = fmaf(f0.y, fmaxf(u[1], 0.f), sfp);
        u[2] = fmaf(C4L2E, a0.z, tnu0.z); den += ex2f(u[2]);
        sabs += fabsf(u[2]); sfp = fmaf(f0.z, fmaxf(u[2], 0.f), sfp);
        u[3] = fmaf(C4L2E, a0.w, tnu0.w); den += ex2f(u[3]);
        sabs += fabsf(u[3]); sfp = fmaf(f0.w, fmaxf(u[3], 0.f), sfp);

        u[4] = fmaf(C4L2E, a1.x, tnu1.x); den += ex2f(u[4]);
        sabs = fmaf(m1, fabsf(u[4]), sabs); sfp = fmaf(f1.x, fmaxf(u[4], 0.f), sfp);
        u[5] = fmaf(C4L2E, a1.y, tnu1.y); den += ex2f(u[5]);
        sabs = fmaf(m1, fabsf(u[5]), sabs); sfp = fmaf(f1.y, fmaxf(u[5], 0.f), sfp);
        u[6] = fmaf(C4L2E, a1.z, tnu1.z); den += ex2f(u[6]);
        sabs = fmaf(m1, fabsf(u[6]), sabs); sfp = fmaf(f1.z, fmaxf(u[6], 0.f), sfp);
        u[7] = fmaf(C4L2E, a1.w, tnu1.w); den += ex2f(u[7]);
        sabs = fmaf(m1, fabsf(u[7]), sabs); sfp = fmaf(f1.w, fmaxf(u[7], 0.f), sfp);

        den = warpSum(den);
        const float L2 = __log2f(den);
        const float Lc = L2 + CLIP2;
        L2sum += L2;

        kacc = fmaf(f0.x, fmaxf(u[0], Lc), kacc);
        kacc = fmaf(f0.y, fmaxf(u[1], Lc), kacc);
        kacc = fmaf(f0.z, fmaxf(u[2], Lc), kacc);
        kacc = fmaf(f0.w, fmaxf(u[3], Lc), kacc);
        kacc = fmaf(f1.x, fmaxf(u[4], Lc), kacc);
        kacc = fmaf(f1.y, fmaxf(u[5], Lc), kacc);
        kacc = fmaf(f1.z, fmaxf(u[6], Lc), kacc);
        kacc = fmaf(f1.w, fmaxf(u[7], Lc), kacc);

        const float s1 = warpSum(sabs - sfp);
        abl[i] = s1 * RC4L2E;

        if (lane == 0 && (c0 + cl) == label) g_al[b] = abl[i];
    }

    // lse + sum over the 5 per-row abl values (once, after the loop)
    float mxw = abl[0];
#pragma unroll
    for (int i = 1; i < NROW; i++) mxw = fmaxf(mxw, abl[i]);
    float sew = 0.f, saw = 0.f;
#pragma unroll
    for (int i = 0; i < NROW; i++) {
        sew += ex2f((abl[i] - mxw) * L2E);
        saw += abl[i];
    }

    kacc = warpSum(kacc);
    if (lane == 0) {
        sh_mx[warp] = mxw;
        sh_se[warp] = sew;
        sh_sa[warp] = saw;
        sh_kp[warp] = -LN2 * (0.5f * kacc - n1 * L2sum);
    }
    __syncthreads();

    // warp 0: combine 8 warp-partials -> 4 scalars for this block
    if (warp == 0) {
        const bool v = lane < 8;
        float m  = v ? sh_mx[lane] : -CUDART_INF_F;
        float se = v ? sh_se[lane] : 0.f;
        float sa = v ? sh_sa[lane] : 0.f;
        float kp = v ? sh_kp[lane] : 0.f;
        const float M = warpMax(m);
        se = se * ex2f((m - M) * L2E);            // -inf lanes -> 0
        se = warpSum(se); sa = warpSum(sa); kp = warpSum(kp);
        if (lane == 0) {
            const int gi = b * GY + blockIdx.y;
            g_bmx[gi] = M; g_bse[gi] = se; g_bsa[gi] = sa; g_bkp[gi] = kp;
        }
    }
    __syncthreads();

    // ---------------- Phase B election: last block of this batch ------------
    if (tid == 0) {
        __threadfence();                        // release this block's partials
        s_flag = (atomicAdd(&g_bcnt[b], 1) == GY - 1);
    }
    __syncthreads();
    if (!s_flag || warp != 0) return;

    // ---------------- Phase B: combine 25 block-partials (warp 0 only) ------
    __threadfence();                            // acquire peers' partials
    {
        const bool v = lane < GY;
        const int gi = b * GY + (v ? lane : 0);
        float m  = v ? g_bmx[gi] : -CUDART_INF_F;
        float se = v ? g_bse[gi] : 0.f;
        float sa = v ? g_bsa[gi] : 0.f;
        float kp = v ? g_bkp[gi] : 0.f;
        const float bmax = warpMax(m);
        se = se * ex2f((m - bmax) * L2E);
        se = warpSum(se); sa = warpSum(sa); kp = warpSum(kp);

        int lastg = 0;
        if (lane == 0) {
            const float L = __logf(se);
            const float al = g_al[b];
            const float ace = -(0.9f * (al - bmax - L) +
                                1e-4f * (sa - (float)NC * (bmax + L)));
            float p1 = 0.f;
            if (n1 > 0.f) p1 = 1.f / (n1 + ((float)HW - n1) * __expf(-10.f));
            g_ace[b] = ace;
            g_kld[b] = p1 * kp;
            __threadfence();
            lastg = (atomicAdd(&g_done, 1) == NB - 1);
        }
        lastg = __shfl_sync(0xffffffffu, lastg, 0);
        if (!lastg) return;
    }

    // ---------------- Phase C: final 64 -> 1 + counter reset ----------------
    __threadfence();                            // acquire all g_ace/g_kld
    {
        float a = g_ace[lane] + g_ace[lane + 32];
        float k = g_kld[lane] + g_kld[lane + 32];
        a = warpSum(a);
        k = warpSum(k);
        g_bcnt[lane] = 0;
        g_bcnt[lane + 32] = 0;
        if (lane == 0) {
            out[0] = (a + 0.5f * k) * (1.0f / NB);
            g_done = 0;
        }
    }
}

extern "C" void kernel_launch(void* const* d_in, const int* in_sizes, int n_in,
                              void* d_out, int out_size) {
    const float* cams  = (const float*)d_in[0];
    const int* y0      = (const int*)d_in[1];
    const int* labels  = (const int*)d_in[2];
    float* out = (float*)d_out;

    k1<<<dim3(NB, GY), 256>>>(cams, y0, labels, out);
}